// round 15
// baseline (speedup 1.0000x reference)
#include <cuda_runtime.h>
#include <cuda_bf16.h>
#include <cstdint>

#define NN 4096
#define DD 256
#define TD 768
#define WPR 128
#define MAXN 512
#define PITCH 72   // bf16 elements per staged smem row (bank-conflict-free)

// ---------------- scratch ----------------------------------------------------
__device__ unsigned int g_bitmap[NN * WPR];
__device__ __align__(16) float g_qkv[NN * TD];
__device__ __align__(16) float g_fin[NN * DD];
__device__ __align__(16) __nv_bfloat16 g_ah[NN * DD];   // ctx hi (attn out)
__device__ __align__(16) __nv_bfloat16 g_al[NN * DD];   // ctx lo
__device__ __align__(16) __nv_bfloat16 g_nh[NN * DD];   // nf hi -> later att hi
__device__ __align__(16) __nv_bfloat16 g_nl[NN * DD];   // nf lo -> later att lo
__device__ __align__(16) __nv_bfloat16 g_wh[TD * DD];   // in_w hi
__device__ __align__(16) __nv_bfloat16 g_wl[TD * DD];   // in_w lo
__device__ __align__(16) __nv_bfloat16 g_oh[DD * DD];   // out_w hi
__device__ __align__(16) __nv_bfloat16 g_ol[DD * DD];   // out_w lo
__device__ __align__(16) __nv_bfloat16 g_ph[DD * DD];   // p_w hi
__device__ __align__(16) __nv_bfloat16 g_pl[DD * DD];   // p_w lo

// ---------------- helpers -----------------------------------------------------
__device__ __forceinline__ uint32_t pack_bf2(float x, float y) {
    __nv_bfloat162 h = __floats2bfloat162_rn(x, y);
    return *(uint32_t*)&h;
}
__device__ __forceinline__ void split2(float x, float y, uint32_t& hi, uint32_t& lo) {
    float hx = __bfloat162float(__float2bfloat16(x));
    float hy = __bfloat162float(__float2bfloat16(y));
    hi = pack_bf2(x, y);
    lo = pack_bf2(x - hx, y - hy);
}
__device__ __forceinline__ void mma_bf16(float* c, const uint32_t* a, const uint32_t* b) {
    asm volatile("mma.sync.aligned.m16n8k16.row.col.f32.bf16.bf16.f32 "
        "{%0,%1,%2,%3}, {%4,%5,%6,%7}, {%8,%9}, {%0,%1,%2,%3};"
        : "+f"(c[0]), "+f"(c[1]), "+f"(c[2]), "+f"(c[3])
        : "r"(a[0]), "r"(a[1]), "r"(a[2]), "r"(a[3]), "r"(b[0]), "r"(b[1]));
}

// ---------------- bitmap + edges ---------------------------------------------
__global__ void k_init_bitmap() {
    int w = blockIdx.x * 256 + threadIdx.x;
    int row = w >> 7, cw = w & 127;
    g_bitmap[w] = ((row >> 5) == cw) ? (1u << (row & 31)) : 0u;
}
__global__ void k_edges(const int* __restrict__ ei, int E) {
    int e = blockIdx.x * 256 + threadIdx.x;
    if (e >= E) return;
    int s = ei[e], d = ei[E + e];
    atomicOr(&g_bitmap[s * WPR + (d >> 5)], 1u << (d & 31));
    atomicOr(&g_bitmap[d * WPR + (s >> 5)], 1u << (s & 31));
}

// ---------------- pre-split all fp32 operands into bf16 hi/lo ------------------
#define NA (NN * DD / 2)     // float2 in nf
#define NW (TD * DD / 2)     // float2 in in_w
#define NO (DD * DD / 2)     // float2 in out_w / p_w
__global__ void k_split_in(const float* __restrict__ nf, const float* __restrict__ in_w,
                           const float* __restrict__ out_w, const float* __restrict__ p_w) {
    int idx = blockIdx.x * 256 + threadIdx.x;
    if (idx < NA) {
        float2 v = ((const float2*)nf)[idx];
        uint32_t hi, lo; split2(v.x, v.y, hi, lo);
        ((uint32_t*)g_nh)[idx] = hi;
        ((uint32_t*)g_nl)[idx] = lo;
    } else if (idx < NA + NW) {
        int j = idx - NA;
        float2 v = ((const float2*)in_w)[j];
        uint32_t hi, lo; split2(v.x, v.y, hi, lo);
        ((uint32_t*)g_wh)[j] = hi;
        ((uint32_t*)g_wl)[j] = lo;
    } else if (idx < NA + NW + NO) {
        int j = idx - NA - NW;
        float2 v = ((const float2*)out_w)[j];
        uint32_t hi, lo; split2(v.x, v.y, hi, lo);
        ((uint32_t*)g_oh)[j] = hi;
        ((uint32_t*)g_ol)[j] = lo;
    } else if (idx < NA + NW + 2 * NO) {
        int j = idx - NA - NW - NO;
        float2 v = ((const float2*)p_w)[j];
        uint32_t hi, lo; split2(v.x, v.y, hi, lo);
        ((uint32_t*)g_ph)[j] = hi;
        ((uint32_t*)g_pl)[j] = lo;
    }
}

// ---------------- split-bf16 tensor-core GEMM (all operands pre-split) --------
// C[M x Nn] = A[M x 256] @ W[Nn x 256]^T + bias (+resid).
// ASRC: 0 = g_nh/g_nl, 1 = g_ah/g_al.  WSRC: 0 = in_w, 1 = out_w, 2 = p_w.
// DST:  0 = g_qkv (fp32), 1 = g_fin (fp32), 2 = split bf16 -> g_nh/g_nl.
template <int BM, int ASRC, int WSRC, int DST, bool QSCALE, bool RESID>
__global__ void __launch_bounds__(256, 2)
k_mgemm(const float* __restrict__ bias, const float* __restrict__ resid, int Nn) {
    constexpr int MF = BM / 32;
    extern __shared__ __nv_bfloat16 sm[];
    __nv_bfloat16* Ah = sm;
    __nv_bfloat16* Al = sm + BM * PITCH;
    __nv_bfloat16* Bh = sm + 2 * BM * PITCH;
    __nv_bfloat16* Bl = sm + 2 * BM * PITCH + 128 * PITCH;
    uint32_t* Ah32 = (uint32_t*)Ah; uint32_t* Al32 = (uint32_t*)Al;
    uint32_t* Bh32 = (uint32_t*)Bh; uint32_t* Bl32 = (uint32_t*)Bl;

    const __nv_bfloat16* GAh = ASRC ? g_ah : g_nh;
    const __nv_bfloat16* GAl = ASRC ? g_al : g_nl;
    const __nv_bfloat16* GWh = (WSRC == 0) ? g_wh : (WSRC == 1 ? g_oh : g_ph);
    const __nv_bfloat16* GWl = (WSRC == 0) ? g_wl : (WSRC == 1 ? g_ol : g_pl);
    float* C = (DST == 0) ? g_qkv : g_fin;

    int t = threadIdx.x, warp = t >> 5, lane = t & 31;
    int wm = warp >> 2, wn = warp & 3;
    int m0 = blockIdx.y * BM;
    int n0 = blockIdx.x * 128;

    float acc[MF][4][4];
#pragma unroll
    for (int i = 0; i < MF; i++)
#pragma unroll
        for (int j = 0; j < 4; j++)
#pragma unroll
            for (int k = 0; k < 4; k++) acc[i][j][k] = 0.f;

    for (int kc = 0; kc < 4; kc++) {
        for (int p = t; p < BM * 8; p += 256) {
            int r = p >> 3, c8 = p & 7;
            const __nv_bfloat16* gh = GAh + (size_t)(m0 + r) * 256 + kc * 64;
            const __nv_bfloat16* gl = GAl + (size_t)(m0 + r) * 256 + kc * 64;
            *(uint4*)(Ah + r * PITCH + c8 * 8) = ((const uint4*)gh)[c8];
            *(uint4*)(Al + r * PITCH + c8 * 8) = ((const uint4*)gl)[c8];
        }
        for (int p = t; p < 128 * 8; p += 256) {
            int r = p >> 3, c8 = p & 7;
            const __nv_bfloat16* gh = GWh + (size_t)(n0 + r) * 256 + kc * 64;
            const __nv_bfloat16* gl = GWl + (size_t)(n0 + r) * 256 + kc * 64;
            *(uint4*)(Bh + r * PITCH + c8 * 8) = ((const uint4*)gh)[c8];
            *(uint4*)(Bl + r * PITCH + c8 * 8) = ((const uint4*)gl)[c8];
        }
        __syncthreads();

#pragma unroll
        for (int ks = 0; ks < 4; ks++) {
            int kq = ks * 8 + (lane & 3);
            uint32_t bh[4][2], bl[4][2];
#pragma unroll
            for (int nf = 0; nf < 4; nf++) {
                int col = wn * 32 + nf * 8 + (lane >> 2);
                bh[nf][0] = Bh32[col * (PITCH / 2) + kq];
                bh[nf][1] = Bh32[col * (PITCH / 2) + kq + 4];
                bl[nf][0] = Bl32[col * (PITCH / 2) + kq];
                bl[nf][1] = Bl32[col * (PITCH / 2) + kq + 4];
            }
#pragma unroll
            for (int mf = 0; mf < MF; mf++) {
                int row = wm * (BM / 2) + mf * 16 + (lane >> 2);
                uint32_t ah[4], al[4];
                ah[0] = Ah32[row * (PITCH / 2) + kq];
                ah[1] = Ah32[(row + 8) * (PITCH / 2) + kq];
                ah[2] = Ah32[row * (PITCH / 2) + kq + 4];
                ah[3] = Ah32[(row + 8) * (PITCH / 2) + kq + 4];
                al[0] = Al32[row * (PITCH / 2) + kq];
                al[1] = Al32[(row + 8) * (PITCH / 2) + kq];
                al[2] = Al32[row * (PITCH / 2) + kq + 4];
                al[3] = Al32[(row + 8) * (PITCH / 2) + kq + 4];
#pragma unroll
                for (int nf = 0; nf < 4; nf++) {
                    mma_bf16(acc[mf][nf], ah, bh[nf]);
                    mma_bf16(acc[mf][nf], ah, bl[nf]);
                    mma_bf16(acc[mf][nf], al, bh[nf]);
                }
            }
        }
        __syncthreads();
    }

#pragma unroll
    for (int mf = 0; mf < MF; mf++) {
        int r0 = m0 + wm * (BM / 2) + mf * 16 + (lane >> 2);
#pragma unroll
        for (int nf = 0; nf < 4; nf++) {
            int c0 = n0 + wn * 32 + nf * 8 + (lane & 3) * 2;
            float b0 = bias[c0], b1 = bias[c0 + 1];
            float v0 = acc[mf][nf][0] + b0, v1 = acc[mf][nf][1] + b1;
            float v2 = acc[mf][nf][2] + b0, v3 = acc[mf][nf][3] + b1;
            if (QSCALE && c0 < 256) { v0 *= 0.125f; v1 *= 0.125f; v2 *= 0.125f; v3 *= 0.125f; }
            if (RESID) {
                const float* rp0 = resid + (size_t)r0 * 256 + c0;
                const float* rp1 = resid + (size_t)(r0 + 8) * 256 + c0;
                v0 += rp0[0]; v1 += rp0[1]; v2 += rp1[0]; v3 += rp1[1];
            }
            if (DST == 2) {
                uint32_t hi, lo;
                split2(v0, v1, hi, lo);
                ((uint32_t*)g_nh)[((size_t)r0 * 256 + c0) / 2] = hi;
                ((uint32_t*)g_nl)[((size_t)r0 * 256 + c0) / 2] = lo;
                split2(v2, v3, hi, lo);
                ((uint32_t*)g_nh)[((size_t)(r0 + 8) * 256 + c0) / 2] = hi;
                ((uint32_t*)g_nl)[((size_t)(r0 + 8) * 256 + c0) / 2] = lo;
            } else {
                *(float2*)(C + (size_t)r0 * Nn + c0) = make_float2(v0, v1);
                *(float2*)(C + (size_t)(r0 + 8) * Nn + c0) = make_float2(v2, v3);
            }
        }
    }
}

// ---------------- sparse masked multi-head attention --------------------------
__global__ void k_attn() {
    int i = blockIdx.x;
    __shared__ float q_s[256];
    __shared__ int   nbr[MAXN];
    __shared__ float sc[MAXN * 4];
    __shared__ float inv_s[4];
    __shared__ int   wsum[4];
    __shared__ int   total;
    __shared__ __align__(16) float4 vred[4][64];

    int t = threadIdx.x;
    int warp = t >> 5, lane = t & 31;
    q_s[t] = g_qkv[i * TD + t];

    unsigned w = 0; int pc = 0;
    if (t < 128) { w = g_bitmap[i * WPR + t]; pc = __popc(w); }
    int excl = 0;
    if (t < 128) {
        int v = pc;
#pragma unroll
        for (int o = 1; o < 32; o <<= 1) {
            int u = __shfl_up_sync(0xffffffffu, v, o);
            if (lane >= o) v += u;
        }
        excl = v - pc;
        if (lane == 31) wsum[warp] = v;
    }
    __syncthreads();
    if (t == 0) {
        int s0 = wsum[0], s1 = wsum[1], s2 = wsum[2], s3 = wsum[3];
        wsum[0] = 0; wsum[1] = s0; wsum[2] = s0 + s1; wsum[3] = s0 + s1 + s2;
        total = s0 + s1 + s2 + s3;
    }
    __syncthreads();
    if (t < 128) {
        int base = wsum[warp] + excl;
        unsigned ww = w; int j = 0;
        while (ww) {
            int b = __ffs(ww) - 1;
            ww &= ww - 1;
            int p = base + j++;
            if (p < MAXN) nbr[p] = t * 32 + b;
        }
    }
    __syncthreads();
    int c = total < MAXN ? total : MAXN;

    float4 qA = *(const float4*)(q_s + lane * 4);
    float4 qB = *(const float4*)(q_s + 128 + lane * 4);
    int hg = lane >> 4;

    for (int n = warp; n < c; n += 8) {
        const float* kr = g_qkv + nbr[n] * TD + 256;
        float4 kA = ((const float4*)kr)[lane];
        float4 kB = ((const float4*)kr)[32 + lane];
        float p0 = kA.x * qA.x + kA.y * qA.y + kA.z * qA.z + kA.w * qA.w;
        float p1 = kB.x * qB.x + kB.y * qB.y + kB.z * qB.z + kB.w * qB.w;
#pragma unroll
        for (int o = 8; o; o >>= 1) {
            p0 += __shfl_xor_sync(0xffffffffu, p0, o);
            p1 += __shfl_xor_sync(0xffffffffu, p1, o);
        }
        if ((lane & 15) == 0) {
            sc[n * 4 + hg] = p0;
            sc[n * 4 + 2 + hg] = p1;
        }
    }
    __syncthreads();

    if (warp < 4) {
        int h = warp;
        float m = -1e30f;
        for (int n = lane; n < c; n += 32) m = fmaxf(m, sc[n * 4 + h]);
#pragma unroll
        for (int o = 16; o; o >>= 1) m = fmaxf(m, __shfl_xor_sync(0xffffffffu, m, o));
        float s = 0.f;
        for (int n = lane; n < c; n += 32) {
            float e = expf(sc[n * 4 + h] - m);
            sc[n * 4 + h] = e;
            s += e;
        }
#pragma unroll
        for (int o = 16; o; o >>= 1) s += __shfl_xor_sync(0xffffffffu, s, o);
        if (lane == 0) inv_s[h] = 1.0f / s;
    }
    __syncthreads();

    int g = t >> 6;
    int q = t & 63;
    int h2 = q >> 4;
    float4 a0 = make_float4(0.f, 0.f, 0.f, 0.f);
    float4 a1 = make_float4(0.f, 0.f, 0.f, 0.f);
    int n = g;
    for (; n + 8 <= c; n += 8) {
        float w0 = sc[n * 4 + h2];
        float w1 = sc[(n + 4) * 4 + h2];
        float4 v0 = *(const float4*)&g_qkv[nbr[n] * TD + 512 + q * 4];
        float4 v1 = *(const float4*)&g_qkv[nbr[n + 4] * TD + 512 + q * 4];
        a0.x += w0 * v0.x; a0.y += w0 * v0.y; a0.z += w0 * v0.z; a0.w += w0 * v0.w;
        a1.x += w1 * v1.x; a1.y += w1 * v1.y; a1.z += w1 * v1.z; a1.w += w1 * v1.w;
    }
    for (; n < c; n += 4) {
        float w0 = sc[n * 4 + h2];
        float4 v0 = *(const float4*)&g_qkv[nbr[n] * TD + 512 + q * 4];
        a0.x += w0 * v0.x; a0.y += w0 * v0.y; a0.z += w0 * v0.z; a0.w += w0 * v0.w;
    }
    a0.x += a1.x; a0.y += a1.y; a0.z += a1.z; a0.w += a1.w;
    vred[g][q] = a0;
    __syncthreads();
    if (t < 64) {
        float4 a = vred[0][t], b = vred[1][t], cc = vred[2][t], d = vred[3][t];
        float inv = inv_s[t >> 4];
        float ox = ((a.x + b.x) + (cc.x + d.x)) * inv;
        float oy = ((a.y + b.y) + (cc.y + d.y)) * inv;
        float oz = ((a.z + b.z) + (cc.z + d.z)) * inv;
        float ow = ((a.w + b.w) + (cc.w + d.w)) * inv;
        uint32_t h0, l0, h1, l1;
        split2(ox, oy, h0, l0);
        split2(oz, ow, h1, l1);
        ((uint32_t*)g_ah)[i * 128 + t * 2]     = h0;
        ((uint32_t*)g_ah)[i * 128 + t * 2 + 1] = h1;
        ((uint32_t*)g_al)[i * 128 + t * 2]     = l0;
        ((uint32_t*)g_al)[i * 128 + t * 2 + 1] = l1;
    }
}

// ---------------- LayerNorm: 4 rows/block, float4/thread ----------------------
__global__ void k_ln(const float* __restrict__ gamma,
                     const float* __restrict__ beta,
                     float* __restrict__ out) {
    int t = threadIdx.x;
    int r = t >> 6, cq = t & 63;
    int row = blockIdx.x * 4 + r;
    int warp = t >> 5, lane = t & 31;
    __shared__ float red[8], red2[8];

    float4 v = *(const float4*)&g_fin[row * 256 + cq * 4];
    float s = v.x + v.y + v.z + v.w;
#pragma unroll
    for (int o = 16; o; o >>= 1) s += __shfl_xor_sync(0xffffffffu, s, o);
    if (lane == 0) red[warp] = s;
    __syncthreads();
    float mu = (red[r * 2] + red[r * 2 + 1]) * (1.0f / 256.0f);

    float dx = v.x - mu, dy = v.y - mu, dz = v.z - mu, dw = v.w - mu;
    float s2 = dx * dx + dy * dy + dz * dz + dw * dw;
#pragma unroll
    for (int o = 16; o; o >>= 1) s2 += __shfl_xor_sync(0xffffffffu, s2, o);
    if (lane == 0) red2[warp] = s2;
    __syncthreads();
    float var = (red2[r * 2] + red2[r * 2 + 1]) * (1.0f / 256.0f);
    float rs = rsqrtf(var + 1e-5f);

    float4 gm = *(const float4*)&gamma[cq * 4];
    float4 bt = *(const float4*)&beta[cq * 4];
    float4 o4;
    o4.x = dx * rs * gm.x + bt.x;
    o4.y = dy * rs * gm.y + bt.y;
    o4.z = dz * rs * gm.z + bt.z;
    o4.w = dw * rs * gm.w + bt.w;
    *(float4*)&out[row * 256 + cq * 4] = o4;
}

// ---------------- launch --------------------------------------------------------
extern "C" void kernel_launch(void* const* d_in, const int* in_sizes, int n_in,
                              void* d_out, int out_size) {
    const float* nf    = (const float*)d_in[0];
    const int*   ei    = (const int*)d_in[1];
    const float* in_w  = (const float*)d_in[2];
    const float* in_b  = (const float*)d_in[3];
    const float* out_w = (const float*)d_in[4];
    const float* out_b = (const float*)d_in[5];
    const float* p_w   = (const float*)d_in[6];
    const float* p_b   = (const float*)d_in[7];
    const float* gamma = (const float*)d_in[8];
    const float* beta  = (const float*)d_in[9];
    int E = in_sizes[1] / 2;

    const int SMEM_64 = (2 * 64 + 2 * 128) * PITCH * 2;   // 55296 B
    cudaFuncSetAttribute(
        (const void*)k_mgemm<64, 0, 0, 0, true,  false>,
        cudaFuncAttributeMaxDynamicSharedMemorySize, SMEM_64);
    cudaFuncSetAttribute(
        (const void*)k_mgemm<64, 1, 1, 2, false, false>,
        cudaFuncAttributeMaxDynamicSharedMemorySize, SMEM_64);
    cudaFuncSetAttribute(
        (const void*)k_mgemm<64, 0, 2, 1, false, true>,
        cudaFuncAttributeMaxDynamicSharedMemorySize, SMEM_64);

    int NSPLIT = NA + NW + 2 * NO;
    k_init_bitmap<<<(NN * WPR) / 256, 256>>>();
    k_edges<<<(E + 255) / 256, 256>>>(ei, E);
    k_split_in<<<(NSPLIT + 255) / 256, 256>>>(nf, in_w, out_w, p_w);
    k_mgemm<64, 0, 0, 0, true, false>
        <<<dim3(TD / 128, NN / 64), 256, SMEM_64>>>(in_b, nullptr, TD);
    k_attn<<<NN, 256>>>();
    k_mgemm<64, 1, 1, 2, false, false>
        <<<dim3(DD / 128, NN / 64), 256, SMEM_64>>>(out_b, nullptr, DD);
    k_mgemm<64, 0, 2, 1, false, true>
        <<<dim3(DD / 128, NN / 64), 256, SMEM_64>>>(p_b, nf, DD);
    k_ln<<<NN / 4, 256>>>(gamma, beta, (float*)d_out);
}

// round 16
// speedup vs baseline: 1.1649x; 1.1649x over previous
#include <cuda_runtime.h>
#include <cuda_bf16.h>
#include <cstdint>

#define NN 4096
#define DD 256
#define TD 768
#define WPR 128
#define MAXN 512
#define PITCH 72   // bf16 elements per staged smem row

// ---------------- scratch ----------------------------------------------------
__device__ unsigned int g_bitmap[NN * WPR];
__device__ __align__(16) float g_qkv[NN * TD];
__device__ __align__(16) float g_fin[NN * DD];
__device__ float g_bc[DD];
__device__ __align__(16) float g_wcp[4][DD * DD];
__device__ __align__(16) __nv_bfloat16 g_ah[NN * DD];
__device__ __align__(16) __nv_bfloat16 g_al[NN * DD];
__device__ __align__(16) __nv_bfloat16 g_nh[NN * DD];
__device__ __align__(16) __nv_bfloat16 g_nl[NN * DD];
__device__ __align__(16) __nv_bfloat16 g_wh[TD * DD];
__device__ __align__(16) __nv_bfloat16 g_wl[TD * DD];
__device__ __align__(16) __nv_bfloat16 g_ch[DD * DD];
__device__ __align__(16) __nv_bfloat16 g_cl[DD * DD];

// ---------------- helpers -----------------------------------------------------
__device__ __forceinline__ uint32_t pack_bf2(float x, float y) {
    __nv_bfloat162 h = __floats2bfloat162_rn(x, y);
    return *(uint32_t*)&h;
}
__device__ __forceinline__ void split2(float x, float y, uint32_t& hi, uint32_t& lo) {
    float hx = __bfloat162float(__float2bfloat16(x));
    float hy = __bfloat162float(__float2bfloat16(y));
    hi = pack_bf2(x, y);
    lo = pack_bf2(x - hx, y - hy);
}
__device__ __forceinline__ void mma_bf16(float* c, const uint32_t* a, const uint32_t* b) {
    asm volatile("mma.sync.aligned.m16n8k16.row.col.f32.bf16.bf16.f32 "
        "{%0,%1,%2,%3}, {%4,%5,%6,%7}, {%8,%9}, {%0,%1,%2,%3};"
        : "+f"(c[0]), "+f"(c[1]), "+f"(c[2]), "+f"(c[3])
        : "r"(a[0]), "r"(a[1]), "r"(a[2]), "r"(a[3]), "r"(b[0]), "r"(b[1]));
}
__device__ __forceinline__ uint32_t smem_u32(const void* p) {
    uint32_t a;
    asm("{ .reg .u64 t; cvta.to.shared.u64 t, %1; cvt.u32.u64 %0, t; }" : "=r"(a) : "l"(p));
    return a;
}
__device__ __forceinline__ void cpa16(uint32_t dst, const void* src) {
    asm volatile("cp.async.cg.shared.global [%0], [%1], 16;" :: "r"(dst), "l"(src));
}
#define CP_COMMIT() asm volatile("cp.async.commit_group;" ::: "memory")

// ---------------- bitmap + edges ---------------------------------------------
__global__ void k_init_bitmap() {
    int w = blockIdx.x * 256 + threadIdx.x;
    int row = w >> 7, cw = w & 127;
    g_bitmap[w] = ((row >> 5) == cw) ? (1u << (row & 31)) : 0u;
}
__global__ void k_edges(const int* __restrict__ ei, int E) {
    int e = blockIdx.x * 256 + threadIdx.x;
    if (e >= E) return;
    int s = ei[e], d = ei[E + e];
    atomicOr(&g_bitmap[s * WPR + (d >> 5)], 1u << (d & 31));
    atomicOr(&g_bitmap[d * WPR + (s >> 5)], 1u << (s & 31));
}

// ---------------- pre-split nf + in_w into bf16 hi/lo -------------------------
#define NA (NN * DD / 2)
#define NW (TD * DD / 2)
__global__ void k_split_in(const float* __restrict__ nf, const float* __restrict__ in_w) {
    int idx = blockIdx.x * 256 + threadIdx.x;
    if (idx < NA) {
        float2 v = ((const float2*)nf)[idx];
        uint32_t hi, lo; split2(v.x, v.y, hi, lo);
        ((uint32_t*)g_nh)[idx] = hi;
        ((uint32_t*)g_nl)[idx] = lo;
    } else if (idx < NA + NW) {
        int j = idx - NA;
        float2 v = ((const float2*)in_w)[j];
        uint32_t hi, lo; split2(v.x, v.y, hi, lo);
        ((uint32_t*)g_wh)[j] = hi;
        ((uint32_t*)g_wl)[j] = lo;
    }
}

// ---------------- weight fusion: Wc = Wp @ Wo, K-split x4 ---------------------
__global__ void k_wc(const float* __restrict__ Wp, const float* __restrict__ Wo,
                     const float* __restrict__ bo, const float* __restrict__ bp) {
    __shared__ float As[32][65];
    __shared__ float Bs[64][34];
    int t = threadIdx.x;
    int m0 = blockIdx.y * 32, n0 = blockIdx.x * 32;
    int z  = blockIdx.z, k0 = z * 64;

    for (int idx = t; idx < 32 * 64; idx += 256) {
        int r = idx >> 6, c = idx & 63;
        As[r][c] = Wp[(m0 + r) * 256 + k0 + c];
    }
    for (int idx = t; idx < 64 * 32; idx += 256) {
        int k = idx >> 5, n = idx & 31;
        Bs[k][n] = Wo[(k0 + k) * 256 + n0 + n];
    }
    __syncthreads();

    int tm = t >> 4, tn = t & 15;
    float a00 = 0.f, a01 = 0.f, a10 = 0.f, a11 = 0.f;
#pragma unroll 8
    for (int kk = 0; kk < 64; kk++) {
        float x0 = As[tm * 2][kk];
        float x1 = As[tm * 2 + 1][kk];
        float2 b = *(float2*)&Bs[kk][tn * 2];
        a00 += x0 * b.x; a01 += x0 * b.y;
        a10 += x1 * b.x; a11 += x1 * b.y;
    }
    float* P = g_wcp[z];
    int row0 = m0 + tm * 2, col = n0 + tn * 2;
    *(float2*)&P[row0 * 256 + col]       = make_float2(a00, a01);
    *(float2*)&P[(row0 + 1) * 256 + col] = make_float2(a10, a11);

    if (blockIdx.x == 0 && z == 0) {
        int r = t >> 3, k8 = t & 7;
        const float4* wr = (const float4*)(Wp + (m0 + r) * 256 + k8 * 32);
        const float4* br = (const float4*)(bo + k8 * 32);
        float s = 0.f;
#pragma unroll
        for (int u = 0; u < 8; u++) {
            float4 w4 = wr[u], b4 = br[u];
            s += w4.x * b4.x + w4.y * b4.y + w4.z * b4.z + w4.w * b4.w;
        }
        s += __shfl_xor_sync(0xffffffffu, s, 4);
        s += __shfl_xor_sync(0xffffffffu, s, 2);
        s += __shfl_xor_sync(0xffffffffu, s, 1);
        if (k8 == 0) g_bc[m0 + r] = s + bp[m0 + r];
    }
}
__global__ void k_wcr() {
    int idx = blockIdx.x * 128 + threadIdx.x;
    float2 p0 = ((const float2*)g_wcp[0])[idx];
    float2 p1 = ((const float2*)g_wcp[1])[idx];
    float2 p2 = ((const float2*)g_wcp[2])[idx];
    float2 p3 = ((const float2*)g_wcp[3])[idx];
    float x = ((p0.x + p1.x) + (p2.x + p3.x));
    float y = ((p0.y + p1.y) + (p2.y + p3.y));
    uint32_t hi, lo; split2(x, y, hi, lo);
    ((uint32_t*)g_ch)[idx] = hi;
    ((uint32_t*)g_cl)[idx] = lo;
}

// ---------------- split-bf16 tensor-core GEMM, cp.async double-buffered -------
// C[M x Nn] = A[M x 256] @ W[Nn x 256]^T + bias (+resid). Operands pre-split.
template <int BM, int ASRC, int WSRC, int DST, bool QSCALE, bool RESID, bool BCBIAS>
__global__ void __launch_bounds__(256, 2)
k_mgemm(const float* __restrict__ bias_ext, const float* __restrict__ resid, int Nn) {
    constexpr int MF = BM / 32;
    constexpr int OFF_AL = BM * PITCH;            // bf16 units within a stage
    constexpr int OFF_BH = 2 * BM * PITCH;
    constexpr int OFF_BL = 2 * BM * PITCH + 128 * PITCH;
    constexpr int STAGE  = (2 * BM + 2 * 128) * PITCH;
    extern __shared__ __nv_bfloat16 sm[];

    const __nv_bfloat16* GAh = ASRC ? g_ah : g_nh;
    const __nv_bfloat16* GAl = ASRC ? g_al : g_nl;
    const __nv_bfloat16* GWh = WSRC ? g_ch : g_wh;
    const __nv_bfloat16* GWl = WSRC ? g_cl : g_wl;
    float* C = DST ? g_fin : g_qkv;
    const float* bias = BCBIAS ? g_bc : bias_ext;

    int t = threadIdx.x, warp = t >> 5, lane = t & 31;
    int wm = warp >> 2, wn = warp & 3;
    int m0 = blockIdx.y * BM;
    int n0 = blockIdx.x * 128;
    uint32_t sbase = smem_u32(sm);

    // async stage of chunk kc into buffer s
    auto issue_stage = [&](int s, int kc) {
        uint32_t sb = sbase + (uint32_t)s * STAGE * 2;
        for (int p = t; p < BM * 8; p += 256) {
            int r = p >> 3, c8 = p & 7;
            uint32_t d = sb + (uint32_t)(r * PITCH + c8 * 8) * 2;
            cpa16(d, (const uint4*)(GAh + (size_t)(m0 + r) * 256 + kc * 64) + c8);
            cpa16(d + OFF_AL * 2, (const uint4*)(GAl + (size_t)(m0 + r) * 256 + kc * 64) + c8);
        }
        for (int p = t; p < 128 * 8; p += 256) {
            int r = p >> 3, c8 = p & 7;
            uint32_t d = sb + (uint32_t)(OFF_BH + r * PITCH + c8 * 8) * 2;
            cpa16(d, (const uint4*)(GWh + (size_t)(n0 + r) * 256 + kc * 64) + c8);
            cpa16(d + 128 * PITCH * 2, (const uint4*)(GWl + (size_t)(n0 + r) * 256 + kc * 64) + c8);
        }
        CP_COMMIT();
    };

    float acc[MF][4][4];
#pragma unroll
    for (int i = 0; i < MF; i++)
#pragma unroll
        for (int j = 0; j < 4; j++)
#pragma unroll
            for (int k = 0; k < 4; k++) acc[i][j][k] = 0.f;

    issue_stage(0, 0);

    for (int kc = 0; kc < 4; kc++) {
        if (kc < 3) {
            issue_stage((kc + 1) & 1, kc + 1);
            asm volatile("cp.async.wait_group 1;" ::: "memory");
        } else {
            asm volatile("cp.async.wait_group 0;" ::: "memory");
        }
        __syncthreads();

        int s = kc & 1;
        uint32_t* Ah32 = (uint32_t*)(sm + (size_t)s * STAGE);
        uint32_t* Al32 = (uint32_t*)(sm + (size_t)s * STAGE + OFF_AL);
        uint32_t* Bh32 = (uint32_t*)(sm + (size_t)s * STAGE + OFF_BH);
        uint32_t* Bl32 = (uint32_t*)(sm + (size_t)s * STAGE + OFF_BL);

#pragma unroll
        for (int ks = 0; ks < 4; ks++) {
            int kq = ks * 8 + (lane & 3);
            uint32_t bh[4][2], bl[4][2];
#pragma unroll
            for (int nf = 0; nf < 4; nf++) {
                int col = wn * 32 + nf * 8 + (lane >> 2);
                bh[nf][0] = Bh32[col * (PITCH / 2) + kq];
                bh[nf][1] = Bh32[col * (PITCH / 2) + kq + 4];
                bl[nf][0] = Bl32[col * (PITCH / 2) + kq];
                bl[nf][1] = Bl32[col * (PITCH / 2) + kq + 4];
            }
#pragma unroll
            for (int mf = 0; mf < MF; mf++) {
                int row = wm * (BM / 2) + mf * 16 + (lane >> 2);
                uint32_t ah[4], al[4];
                ah[0] = Ah32[row * (PITCH / 2) + kq];
                ah[1] = Ah32[(row + 8) * (PITCH / 2) + kq];
                ah[2] = Ah32[row * (PITCH / 2) + kq + 4];
                ah[3] = Ah32[(row + 8) * (PITCH / 2) + kq + 4];
                al[0] = Al32[row * (PITCH / 2) + kq];
                al[1] = Al32[(row + 8) * (PITCH / 2) + kq];
                al[2] = Al32[row * (PITCH / 2) + kq + 4];
                al[3] = Al32[(row + 8) * (PITCH / 2) + kq + 4];
#pragma unroll
                for (int nf = 0; nf < 4; nf++) {
                    mma_bf16(acc[mf][nf], ah, bh[nf]);
                    mma_bf16(acc[mf][nf], ah, bl[nf]);
                    mma_bf16(acc[mf][nf], al, bh[nf]);
                }
            }
        }
        __syncthreads();
    }

#pragma unroll
    for (int mf = 0; mf < MF; mf++) {
        int r0 = m0 + wm * (BM / 2) + mf * 16 + (lane >> 2);
#pragma unroll
        for (int nf = 0; nf < 4; nf++) {
            int c0 = n0 + wn * 32 + nf * 8 + (lane & 3) * 2;
            float b0 = bias[c0], b1 = bias[c0 + 1];
            float v0 = acc[mf][nf][0] + b0, v1 = acc[mf][nf][1] + b1;
            float v2 = acc[mf][nf][2] + b0, v3 = acc[mf][nf][3] + b1;
            if (QSCALE && c0 < 256) { v0 *= 0.125f; v1 *= 0.125f; v2 *= 0.125f; v3 *= 0.125f; }
            if (RESID) {
                const float* rp0 = resid + (size_t)r0 * 256 + c0;
                const float* rp1 = resid + (size_t)(r0 + 8) * 256 + c0;
                v0 += rp0[0]; v1 += rp0[1]; v2 += rp1[0]; v3 += rp1[1];
            }
            *(float2*)(C + (size_t)r0 * Nn + c0) = make_float2(v0, v1);
            *(float2*)(C + (size_t)(r0 + 8) * Nn + c0) = make_float2(v2, v3);
        }
    }
}

// ---------------- sparse masked multi-head attention --------------------------
__global__ void k_attn() {
    int i = blockIdx.x;
    __shared__ float q_s[256];
    __shared__ int   nbr[MAXN];
    __shared__ float sc[MAXN * 4];
    __shared__ float inv_s[4];
    __shared__ int   wsum[4];
    __shared__ int   total;
    __shared__ __align__(16) float4 vred[4][64];

    int t = threadIdx.x;
    int warp = t >> 5, lane = t & 31;
    q_s[t] = g_qkv[i * TD + t];

    unsigned w = 0; int pc = 0;
    if (t < 128) { w = g_bitmap[i * WPR + t]; pc = __popc(w); }
    int excl = 0;
    if (t < 128) {
        int v = pc;
#pragma unroll
        for (int o = 1; o < 32; o <<= 1) {
            int u = __shfl_up_sync(0xffffffffu, v, o);
            if (lane >= o) v += u;
        }
        excl = v - pc;
        if (lane == 31) wsum[warp] = v;
    }
    __syncthreads();
    if (t == 0) {
        int s0 = wsum[0], s1 = wsum[1], s2 = wsum[2], s3 = wsum[3];
        wsum[0] = 0; wsum[1] = s0; wsum[2] = s0 + s1; wsum[3] = s0 + s1 + s2;
        total = s0 + s1 + s2 + s3;
    }
    __syncthreads();
    if (t < 128) {
        int base = wsum[warp] + excl;
        unsigned ww = w; int j = 0;
        while (ww) {
            int b = __ffs(ww) - 1;
            ww &= ww - 1;
            int p = base + j++;
            if (p < MAXN) nbr[p] = t * 32 + b;
        }
    }
    __syncthreads();
    int c = total < MAXN ? total : MAXN;

    float4 qA = *(const float4*)(q_s + lane * 4);
    float4 qB = *(const float4*)(q_s + 128 + lane * 4);
    int hg = lane >> 4;

    for (int n = warp; n < c; n += 8) {
        const float* kr = g_qkv + nbr[n] * TD + 256;
        float4 kA = ((const float4*)kr)[lane];
        float4 kB = ((const float4*)kr)[32 + lane];
        float p0 = kA.x * qA.x + kA.y * qA.y + kA.z * qA.z + kA.w * qA.w;
        float p1 = kB.x * qB.x + kB.y * qB.y + kB.z * qB.z + kB.w * qB.w;
#pragma unroll
        for (int o = 8; o; o >>= 1) {
            p0 += __shfl_xor_sync(0xffffffffu, p0, o);
            p1 += __shfl_xor_sync(0xffffffffu, p1, o);
        }
        if ((lane & 15) == 0) {
            sc[n * 4 + hg] = p0;
            sc[n * 4 + 2 + hg] = p1;
        }
    }
    __syncthreads();

    if (warp < 4) {
        int h = warp;
        float m = -1e30f;
        for (int n = lane; n < c; n += 32) m = fmaxf(m, sc[n * 4 + h]);
#pragma unroll
        for (int o = 16; o; o >>= 1) m = fmaxf(m, __shfl_xor_sync(0xffffffffu, m, o));
        float s = 0.f;
        for (int n = lane; n < c; n += 32) {
            float e = expf(sc[n * 4 + h] - m);
            sc[n * 4 + h] = e;
            s += e;
        }
#pragma unroll
        for (int o = 16; o; o >>= 1) s += __shfl_xor_sync(0xffffffffu, s, o);
        if (lane == 0) inv_s[h] = 1.0f / s;
    }
    __syncthreads();

    int g = t >> 6;
    int q = t & 63;
    int h2 = q >> 4;
    float4 a0 = make_float4(0.f, 0.f, 0.f, 0.f);
    float4 a1 = make_float4(0.f, 0.f, 0.f, 0.f);
    int n = g;
    for (; n + 8 <= c; n += 8) {
        float w0 = sc[n * 4 + h2];
        float w1 = sc[(n + 4) * 4 + h2];
        float4 v0 = *(const float4*)&g_qkv[nbr[n] * TD + 512 + q * 4];
        float4 v1 = *(const float4*)&g_qkv[nbr[n + 4] * TD + 512 + q * 4];
        a0.x += w0 * v0.x; a0.y += w0 * v0.y; a0.z += w0 * v0.z; a0.w += w0 * v0.w;
        a1.x += w1 * v1.x; a1.y += w1 * v1.y; a1.z += w1 * v1.z; a1.w += w1 * v1.w;
    }
    for (; n < c; n += 4) {
        float w0 = sc[n * 4 + h2];
        float4 v0 = *(const float4*)&g_qkv[nbr[n] * TD + 512 + q * 4];
        a0.x += w0 * v0.x; a0.y += w0 * v0.y; a0.z += w0 * v0.z; a0.w += w0 * v0.w;
    }
    a0.x += a1.x; a0.y += a1.y; a0.z += a1.z; a0.w += a1.w;
    vred[g][q] = a0;
    __syncthreads();
    if (t < 64) {
        float4 a = vred[0][t], b = vred[1][t], cc = vred[2][t], d = vred[3][t];
        float inv = inv_s[t >> 4];
        float ox = ((a.x + b.x) + (cc.x + d.x)) * inv;
        float oy = ((a.y + b.y) + (cc.y + d.y)) * inv;
        float oz = ((a.z + b.z) + (cc.z + d.z)) * inv;
        float ow = ((a.w + b.w) + (cc.w + d.w)) * inv;
        uint32_t h0, l0, h1, l1;
        split2(ox, oy, h0, l0);
        split2(oz, ow, h1, l1);
        ((uint32_t*)g_ah)[i * 128 + t * 2]     = h0;
        ((uint32_t*)g_ah)[i * 128 + t * 2 + 1] = h1;
        ((uint32_t*)g_al)[i * 128 + t * 2]     = l0;
        ((uint32_t*)g_al)[i * 128 + t * 2 + 1] = l1;
    }
}

// ---------------- LayerNorm: 4 rows/block, float4/thread ----------------------
__global__ void k_ln(const float* __restrict__ gamma,
                     const float* __restrict__ beta,
                     float* __restrict__ out) {
    int t = threadIdx.x;
    int r = t >> 6, cq = t & 63;
    int row = blockIdx.x * 4 + r;
    int warp = t >> 5, lane = t & 31;
    __shared__ float red[8], red2[8];

    float4 v = *(const float4*)&g_fin[row * 256 + cq * 4];
    float s = v.x + v.y + v.z + v.w;
#pragma unroll
    for (int o = 16; o; o >>= 1) s += __shfl_xor_sync(0xffffffffu, s, o);
    if (lane == 0) red[warp] = s;
    __syncthreads();
    float mu = (red[r * 2] + red[r * 2 + 1]) * (1.0f / 256.0f);

    float dx = v.x - mu, dy = v.y - mu, dz = v.z - mu, dw = v.w - mu;
    float s2 = dx * dx + dy * dy + dz * dz + dw * dw;
#pragma unroll
    for (int o = 16; o; o >>= 1) s2 += __shfl_xor_sync(0xffffffffu, s2, o);
    if (lane == 0) red2[warp] = s2;
    __syncthreads();
    float var = (red2[r * 2] + red2[r * 2 + 1]) * (1.0f / 256.0f);
    float rs = rsqrtf(var + 1e-5f);

    float4 gm = *(const float4*)&gamma[cq * 4];
    float4 bt = *(const float4*)&beta[cq * 4];
    float4 o4;
    o4.x = dx * rs * gm.x + bt.x;
    o4.y = dy * rs * gm.y + bt.y;
    o4.z = dz * rs * gm.z + bt.z;
    o4.w = dw * rs * gm.w + bt.w;
    *(float4*)&out[row * 256 + cq * 4] = o4;
}

// ---------------- launch --------------------------------------------------------
extern "C" void kernel_launch(void* const* d_in, const int* in_sizes, int n_in,
                              void* d_out, int out_size) {
    const float* nf    = (const float*)d_in[0];
    const int*   ei    = (const int*)d_in[1];
    const float* in_w  = (const float*)d_in[2];
    const float* in_b  = (const float*)d_in[3];
    const float* out_w = (const float*)d_in[4];
    const float* out_b = (const float*)d_in[5];
    const float* p_w   = (const float*)d_in[6];
    const float* p_b   = (const float*)d_in[7];
    const float* gamma = (const float*)d_in[8];
    const float* beta  = (const float*)d_in[9];
    int E = in_sizes[1] / 2;

    const int SMEM_64 = 2 * (2 * 64 + 2 * 128) * PITCH * 2;   // 110592 B (2 stages)
    cudaFuncSetAttribute(
        (const void*)k_mgemm<64, 0, 0, 0, true,  false, false>,
        cudaFuncAttributeMaxDynamicSharedMemorySize, SMEM_64);
    cudaFuncSetAttribute(
        (const void*)k_mgemm<64, 1, 1, 1, false, true,  true>,
        cudaFuncAttributeMaxDynamicSharedMemorySize, SMEM_64);

    k_init_bitmap<<<(NN * WPR) / 256, 256>>>();
    k_edges<<<(E + 255) / 256, 256>>>(ei, E);
    k_split_in<<<(NA + NW + 255) / 256, 256>>>(nf, in_w);
    k_wc<<<dim3(8, 8, 4), 256>>>(p_w, out_w, out_b, p_b);
    k_wcr<<<256, 128>>>();
    k_mgemm<64, 0, 0, 0, true, false, false>
        <<<dim3(TD / 128, NN / 64), 256, SMEM_64>>>(in_b, nullptr, TD);
    k_attn<<<NN, 256>>>();
    k_mgemm<64, 1, 1, 1, false, true, true>
        <<<dim3(DD / 128, NN / 64), 256, SMEM_64>>>(nullptr, nf, DD);
    k_ln<<<NN / 4, 256>>>(gamma, beta, (float*)d_out);
}

// round 17
// speedup vs baseline: 1.2069x; 1.0361x over previous
#include <cuda_runtime.h>
#include <cuda_bf16.h>
#include <cstdint>

#define NN 4096
#define DD 256
#define TD 768
#define WPR 128
#define MAXN 512
#define PITCH 72   // bf16 elements per staged smem row

// ---------------- scratch ----------------------------------------------------
__device__ unsigned int g_bitmap[NN * WPR];
__device__ __align__(16) float g_qkv[NN * TD];
__device__ __align__(16) float g_fin[NN * DD];
__device__ float g_bc[DD];
__device__ __align__(16) float g_wcp[4][DD * DD];
__device__ __align__(16) __nv_bfloat16 g_vh[NN * DD];   // V in bf16 (attn gather)
__device__ __align__(16) __nv_bfloat16 g_ah[NN * DD];
__device__ __align__(16) __nv_bfloat16 g_al[NN * DD];
__device__ __align__(16) __nv_bfloat16 g_nh[NN * DD];
__device__ __align__(16) __nv_bfloat16 g_nl[NN * DD];
__device__ __align__(16) __nv_bfloat16 g_wh[TD * DD];
__device__ __align__(16) __nv_bfloat16 g_wl[TD * DD];
__device__ __align__(16) __nv_bfloat16 g_ch[DD * DD];
__device__ __align__(16) __nv_bfloat16 g_cl[DD * DD];

// ---------------- helpers -----------------------------------------------------
__device__ __forceinline__ uint32_t pack_bf2(float x, float y) {
    __nv_bfloat162 h = __floats2bfloat162_rn(x, y);
    return *(uint32_t*)&h;
}
__device__ __forceinline__ void split2(float x, float y, uint32_t& hi, uint32_t& lo) {
    float hx = __bfloat162float(__float2bfloat16(x));
    float hy = __bfloat162float(__float2bfloat16(y));
    hi = pack_bf2(x, y);
    lo = pack_bf2(x - hx, y - hy);
}
__device__ __forceinline__ void mma_bf16(float* c, const uint32_t* a, const uint32_t* b) {
    asm volatile("mma.sync.aligned.m16n8k16.row.col.f32.bf16.bf16.f32 "
        "{%0,%1,%2,%3}, {%4,%5,%6,%7}, {%8,%9}, {%0,%1,%2,%3};"
        : "+f"(c[0]), "+f"(c[1]), "+f"(c[2]), "+f"(c[3])
        : "r"(a[0]), "r"(a[1]), "r"(a[2]), "r"(a[3]), "r"(b[0]), "r"(b[1]));
}
__device__ __forceinline__ uint32_t smem_u32(const void* p) {
    uint32_t a;
    asm("{ .reg .u64 t; cvta.to.shared.u64 t, %1; cvt.u32.u64 %0, t; }" : "=r"(a) : "l"(p));
    return a;
}
__device__ __forceinline__ void cpa16(uint32_t dst, const void* src) {
    asm volatile("cp.async.cg.shared.global [%0], [%1], 16;" :: "r"(dst), "l"(src));
}
#define CP_COMMIT() asm volatile("cp.async.commit_group;" ::: "memory")

// ---------------- bitmap + edges ---------------------------------------------
__global__ void k_init_bitmap() {
    int w = blockIdx.x * 256 + threadIdx.x;
    int row = w >> 7, cw = w & 127;
    g_bitmap[w] = ((row >> 5) == cw) ? (1u << (row & 31)) : 0u;
}
__global__ void k_edges(const int* __restrict__ ei, int E) {
    int e = blockIdx.x * 256 + threadIdx.x;
    if (e >= E) return;
    int s = ei[e], d = ei[E + e];
    atomicOr(&g_bitmap[s * WPR + (d >> 5)], 1u << (d & 31));
    atomicOr(&g_bitmap[d * WPR + (s >> 5)], 1u << (s & 31));
}

// ---------------- pre-split nf + in_w into bf16 hi/lo -------------------------
#define NA (NN * DD / 2)
#define NW (TD * DD / 2)
__global__ void k_split_in(const float* __restrict__ nf, const float* __restrict__ in_w) {
    int idx = blockIdx.x * 256 + threadIdx.x;
    if (idx < NA) {
        float2 v = ((const float2*)nf)[idx];
        uint32_t hi, lo; split2(v.x, v.y, hi, lo);
        ((uint32_t*)g_nh)[idx] = hi;
        ((uint32_t*)g_nl)[idx] = lo;
    } else if (idx < NA + NW) {
        int j = idx - NA;
        float2 v = ((const float2*)in_w)[j];
        uint32_t hi, lo; split2(v.x, v.y, hi, lo);
        ((uint32_t*)g_wh)[j] = hi;
        ((uint32_t*)g_wl)[j] = lo;
    }
}

// ---------------- weight fusion: Wc = Wp @ Wo, K-split x4 ---------------------
__global__ void k_wc(const float* __restrict__ Wp, const float* __restrict__ Wo,
                     const float* __restrict__ bo, const float* __restrict__ bp) {
    __shared__ float As[32][65];
    __shared__ float Bs[64][34];
    int t = threadIdx.x;
    int m0 = blockIdx.y * 32, n0 = blockIdx.x * 32;
    int z  = blockIdx.z, k0 = z * 64;

    for (int idx = t; idx < 32 * 64; idx += 256) {
        int r = idx >> 6, c = idx & 63;
        As[r][c] = Wp[(m0 + r) * 256 + k0 + c];
    }
    for (int idx = t; idx < 64 * 32; idx += 256) {
        int k = idx >> 5, n = idx & 31;
        Bs[k][n] = Wo[(k0 + k) * 256 + n0 + n];
    }
    __syncthreads();

    int tm = t >> 4, tn = t & 15;
    float a00 = 0.f, a01 = 0.f, a10 = 0.f, a11 = 0.f;
#pragma unroll 8
    for (int kk = 0; kk < 64; kk++) {
        float x0 = As[tm * 2][kk];
        float x1 = As[tm * 2 + 1][kk];
        float2 b = *(float2*)&Bs[kk][tn * 2];
        a00 += x0 * b.x; a01 += x0 * b.y;
        a10 += x1 * b.x; a11 += x1 * b.y;
    }
    float* P = g_wcp[z];
    int row0 = m0 + tm * 2, col = n0 + tn * 2;
    *(float2*)&P[row0 * 256 + col]       = make_float2(a00, a01);
    *(float2*)&P[(row0 + 1) * 256 + col] = make_float2(a10, a11);

    if (blockIdx.x == 0 && z == 0) {
        int r = t >> 3, k8 = t & 7;
        const float4* wr = (const float4*)(Wp + (m0 + r) * 256 + k8 * 32);
        const float4* br = (const float4*)(bo + k8 * 32);
        float s = 0.f;
#pragma unroll
        for (int u = 0; u < 8; u++) {
            float4 w4 = wr[u], b4 = br[u];
            s += w4.x * b4.x + w4.y * b4.y + w4.z * b4.z + w4.w * b4.w;
        }
        s += __shfl_xor_sync(0xffffffffu, s, 4);
        s += __shfl_xor_sync(0xffffffffu, s, 2);
        s += __shfl_xor_sync(0xffffffffu, s, 1);
        if (k8 == 0) g_bc[m0 + r] = s + bp[m0 + r];
    }
}
__global__ void k_wcr() {
    int idx = blockIdx.x * 128 + threadIdx.x;
    float2 p0 = ((const float2*)g_wcp[0])[idx];
    float2 p1 = ((const float2*)g_wcp[1])[idx];
    float2 p2 = ((const float2*)g_wcp[2])[idx];
    float2 p3 = ((const float2*)g_wcp[3])[idx];
    float x = ((p0.x + p1.x) + (p2.x + p3.x));
    float y = ((p0.y + p1.y) + (p2.y + p3.y));
    uint32_t hi, lo; split2(x, y, hi, lo);
    ((uint32_t*)g_ch)[idx] = hi;
    ((uint32_t*)g_cl)[idx] = lo;
}

// ---------------- split-bf16 tensor-core GEMM, cp.async double-buffered -------
// VOUT: also write bf16 V (cols >= 512) to g_vh for the attention gather.
template <int BM, int ASRC, int WSRC, int DST, bool QSCALE, bool RESID, bool BCBIAS, bool VOUT>
__global__ void __launch_bounds__(256, 2)
k_mgemm(const float* __restrict__ bias_ext, const float* __restrict__ resid, int Nn) {
    constexpr int MF = BM / 32;
    constexpr int OFF_AL = BM * PITCH;
    constexpr int OFF_BH = 2 * BM * PITCH;
    constexpr int OFF_BL = 2 * BM * PITCH + 128 * PITCH;
    constexpr int STAGE  = (2 * BM + 2 * 128) * PITCH;
    extern __shared__ __nv_bfloat16 sm[];

    const __nv_bfloat16* GAh = ASRC ? g_ah : g_nh;
    const __nv_bfloat16* GAl = ASRC ? g_al : g_nl;
    const __nv_bfloat16* GWh = WSRC ? g_ch : g_wh;
    const __nv_bfloat16* GWl = WSRC ? g_cl : g_wl;
    float* C = DST ? g_fin : g_qkv;
    const float* bias = BCBIAS ? g_bc : bias_ext;

    int t = threadIdx.x, warp = t >> 5, lane = t & 31;
    int wm = warp >> 2, wn = warp & 3;
    int m0 = blockIdx.y * BM;
    int n0 = blockIdx.x * 128;
    uint32_t sbase = smem_u32(sm);

    auto issue_stage = [&](int s, int kc) {
        uint32_t sb = sbase + (uint32_t)s * STAGE * 2;
        for (int p = t; p < BM * 8; p += 256) {
            int r = p >> 3, c8 = p & 7;
            uint32_t d = sb + (uint32_t)(r * PITCH + c8 * 8) * 2;
            cpa16(d, (const uint4*)(GAh + (size_t)(m0 + r) * 256 + kc * 64) + c8);
            cpa16(d + OFF_AL * 2, (const uint4*)(GAl + (size_t)(m0 + r) * 256 + kc * 64) + c8);
        }
        for (int p = t; p < 128 * 8; p += 256) {
            int r = p >> 3, c8 = p & 7;
            uint32_t d = sb + (uint32_t)(OFF_BH + r * PITCH + c8 * 8) * 2;
            cpa16(d, (const uint4*)(GWh + (size_t)(n0 + r) * 256 + kc * 64) + c8);
            cpa16(d + 128 * PITCH * 2, (const uint4*)(GWl + (size_t)(n0 + r) * 256 + kc * 64) + c8);
        }
        CP_COMMIT();
    };

    float acc[MF][4][4];
#pragma unroll
    for (int i = 0; i < MF; i++)
#pragma unroll
        for (int j = 0; j < 4; j++)
#pragma unroll
            for (int k = 0; k < 4; k++) acc[i][j][k] = 0.f;

    issue_stage(0, 0);

    for (int kc = 0; kc < 4; kc++) {
        if (kc < 3) {
            issue_stage((kc + 1) & 1, kc + 1);
            asm volatile("cp.async.wait_group 1;" ::: "memory");
        } else {
            asm volatile("cp.async.wait_group 0;" ::: "memory");
        }
        __syncthreads();

        int s = kc & 1;
        uint32_t* Ah32 = (uint32_t*)(sm + (size_t)s * STAGE);
        uint32_t* Al32 = (uint32_t*)(sm + (size_t)s * STAGE + OFF_AL);
        uint32_t* Bh32 = (uint32_t*)(sm + (size_t)s * STAGE + OFF_BH);
        uint32_t* Bl32 = (uint32_t*)(sm + (size_t)s * STAGE + OFF_BL);

#pragma unroll
        for (int ks = 0; ks < 4; ks++) {
            int kq = ks * 8 + (lane & 3);
            uint32_t bh[4][2], bl[4][2];
#pragma unroll
            for (int nf = 0; nf < 4; nf++) {
                int col = wn * 32 + nf * 8 + (lane >> 2);
                bh[nf][0] = Bh32[col * (PITCH / 2) + kq];
                bh[nf][1] = Bh32[col * (PITCH / 2) + kq + 4];
                bl[nf][0] = Bl32[col * (PITCH / 2) + kq];
                bl[nf][1] = Bl32[col * (PITCH / 2) + kq + 4];
            }
#pragma unroll
            for (int mf = 0; mf < MF; mf++) {
                int row = wm * (BM / 2) + mf * 16 + (lane >> 2);
                uint32_t ah[4], al[4];
                ah[0] = Ah32[row * (PITCH / 2) + kq];
                ah[1] = Ah32[(row + 8) * (PITCH / 2) + kq];
                ah[2] = Ah32[row * (PITCH / 2) + kq + 4];
                ah[3] = Ah32[(row + 8) * (PITCH / 2) + kq + 4];
                al[0] = Al32[row * (PITCH / 2) + kq];
                al[1] = Al32[(row + 8) * (PITCH / 2) + kq];
                al[2] = Al32[row * (PITCH / 2) + kq + 4];
                al[3] = Al32[(row + 8) * (PITCH / 2) + kq + 4];
#pragma unroll
                for (int nf = 0; nf < 4; nf++) {
                    mma_bf16(acc[mf][nf], ah, bh[nf]);
                    mma_bf16(acc[mf][nf], ah, bl[nf]);
                    mma_bf16(acc[mf][nf], al, bh[nf]);
                }
            }
        }
        __syncthreads();
    }

#pragma unroll
    for (int mf = 0; mf < MF; mf++) {
        int r0 = m0 + wm * (BM / 2) + mf * 16 + (lane >> 2);
#pragma unroll
        for (int nf = 0; nf < 4; nf++) {
            int c0 = n0 + wn * 32 + nf * 8 + (lane & 3) * 2;
            float b0 = bias[c0], b1 = bias[c0 + 1];
            float v0 = acc[mf][nf][0] + b0, v1 = acc[mf][nf][1] + b1;
            float v2 = acc[mf][nf][2] + b0, v3 = acc[mf][nf][3] + b1;
            if (QSCALE && c0 < 256) { v0 *= 0.125f; v1 *= 0.125f; v2 *= 0.125f; v3 *= 0.125f; }
            if (RESID) {
                const float* rp0 = resid + (size_t)r0 * 256 + c0;
                const float* rp1 = resid + (size_t)(r0 + 8) * 256 + c0;
                v0 += rp0[0]; v1 += rp0[1]; v2 += rp1[0]; v3 += rp1[1];
            }
            *(float2*)(C + (size_t)r0 * Nn + c0) = make_float2(v0, v1);
            *(float2*)(C + (size_t)(r0 + 8) * Nn + c0) = make_float2(v2, v3);
            if (VOUT && c0 >= 512) {
                int vc = c0 - 512;
                *(__nv_bfloat162*)(g_vh + (size_t)r0 * 256 + vc) = __floats2bfloat162_rn(v0, v1);
                *(__nv_bfloat162*)(g_vh + (size_t)(r0 + 8) * 256 + vc) = __floats2bfloat162_rn(v2, v3);
            }
        }
    }
}

// ---------------- sparse masked multi-head attention (V in bf16) --------------
__global__ void k_attn() {
    int i = blockIdx.x;
    __shared__ float q_s[256];
    __shared__ int   nbr[MAXN];
    __shared__ float sc[MAXN * 4];
    __shared__ float inv_s[4];
    __shared__ int   wsum[4];
    __shared__ int   total;
    __shared__ __align__(16) float4 vred[4][64];

    int t = threadIdx.x;
    int warp = t >> 5, lane = t & 31;
    q_s[t] = g_qkv[i * TD + t];

    unsigned w = 0; int pc = 0;
    if (t < 128) { w = g_bitmap[i * WPR + t]; pc = __popc(w); }
    int excl = 0;
    if (t < 128) {
        int v = pc;
#pragma unroll
        for (int o = 1; o < 32; o <<= 1) {
            int u = __shfl_up_sync(0xffffffffu, v, o);
            if (lane >= o) v += u;
        }
        excl = v - pc;
        if (lane == 31) wsum[warp] = v;
    }
    __syncthreads();
    if (t == 0) {
        int s0 = wsum[0], s1 = wsum[1], s2 = wsum[2], s3 = wsum[3];
        wsum[0] = 0; wsum[1] = s0; wsum[2] = s0 + s1; wsum[3] = s0 + s1 + s2;
        total = s0 + s1 + s2 + s3;
    }
    __syncthreads();
    if (t < 128) {
        int base = wsum[warp] + excl;
        unsigned ww = w; int j = 0;
        while (ww) {
            int b = __ffs(ww) - 1;
            ww &= ww - 1;
            int p = base + j++;
            if (p < MAXN) nbr[p] = t * 32 + b;
        }
    }
    __syncthreads();
    int c = total < MAXN ? total : MAXN;

    float4 qA = *(const float4*)(q_s + lane * 4);
    float4 qB = *(const float4*)(q_s + 128 + lane * 4);
    int hg = lane >> 4;

    for (int n = warp; n < c; n += 8) {
        const float* kr = g_qkv + nbr[n] * TD + 256;
        float4 kA = ((const float4*)kr)[lane];
        float4 kB = ((const float4*)kr)[32 + lane];
        float p0 = kA.x * qA.x + kA.y * qA.y + kA.z * qA.z + kA.w * qA.w;
        float p1 = kB.x * qB.x + kB.y * qB.y + kB.z * qB.z + kB.w * qB.w;
#pragma unroll
        for (int o = 8; o; o >>= 1) {
            p0 += __shfl_xor_sync(0xffffffffu, p0, o);
            p1 += __shfl_xor_sync(0xffffffffu, p1, o);
        }
        if ((lane & 15) == 0) {
            sc[n * 4 + hg] = p0;
            sc[n * 4 + 2 + hg] = p1;
        }
    }
    __syncthreads();

    if (warp < 4) {
        int h = warp;
        float m = -1e30f;
        for (int n = lane; n < c; n += 32) m = fmaxf(m, sc[n * 4 + h]);
#pragma unroll
        for (int o = 16; o; o >>= 1) m = fmaxf(m, __shfl_xor_sync(0xffffffffu, m, o));
        float s = 0.f;
        for (int n = lane; n < c; n += 32) {
            float e = expf(sc[n * 4 + h] - m);
            sc[n * 4 + h] = e;
            s += e;
        }
#pragma unroll
        for (int o = 16; o; o >>= 1) s += __shfl_xor_sync(0xffffffffu, s, o);
        if (lane == 0) inv_s[h] = 1.0f / s;
    }
    __syncthreads();

    // context: bf16 V gather (8B/thread), 2x unroll, smem reduce
    int g = t >> 6;
    int q = t & 63;
    int h2 = q >> 4;
    float4 a0 = make_float4(0.f, 0.f, 0.f, 0.f);
    float4 a1 = make_float4(0.f, 0.f, 0.f, 0.f);
    int n = g;
    for (; n + 8 <= c; n += 8) {
        float w0 = sc[n * 4 + h2];
        float w1 = sc[(n + 4) * 4 + h2];
        uint2 r0 = *(const uint2*)(g_vh + nbr[n] * 256 + q * 4);
        uint2 r1 = *(const uint2*)(g_vh + nbr[n + 4] * 256 + q * 4);
        float2 f00 = __bfloat1622float2(*(__nv_bfloat162*)&r0.x);
        float2 f01 = __bfloat1622float2(*(__nv_bfloat162*)&r0.y);
        float2 f10 = __bfloat1622float2(*(__nv_bfloat162*)&r1.x);
        float2 f11 = __bfloat1622float2(*(__nv_bfloat162*)&r1.y);
        a0.x += w0 * f00.x; a0.y += w0 * f00.y; a0.z += w0 * f01.x; a0.w += w0 * f01.y;
        a1.x += w1 * f10.x; a1.y += w1 * f10.y; a1.z += w1 * f11.x; a1.w += w1 * f11.y;
    }
    for (; n < c; n += 4) {
        float w0 = sc[n * 4 + h2];
        uint2 r0 = *(const uint2*)(g_vh + nbr[n] * 256 + q * 4);
        float2 f00 = __bfloat1622float2(*(__nv_bfloat162*)&r0.x);
        float2 f01 = __bfloat1622float2(*(__nv_bfloat162*)&r0.y);
        a0.x += w0 * f00.x; a0.y += w0 * f00.y; a0.z += w0 * f01.x; a0.w += w0 * f01.y;
    }
    a0.x += a1.x; a0.y += a1.y; a0.z += a1.z; a0.w += a1.w;
    vred[g][q] = a0;
    __syncthreads();
    if (t < 64) {
        float4 a = vred[0][t], b = vred[1][t], cc = vred[2][t], d = vred[3][t];
        float inv = inv_s[t >> 4];
        float ox = ((a.x + b.x) + (cc.x + d.x)) * inv;
        float oy = ((a.y + b.y) + (cc.y + d.y)) * inv;
        float oz = ((a.z + b.z) + (cc.z + d.z)) * inv;
        float ow = ((a.w + b.w) + (cc.w + d.w)) * inv;
        uint32_t h0, l0, h1, l1;
        split2(ox, oy, h0, l0);
        split2(oz, ow, h1, l1);
        ((uint32_t*)g_ah)[i * 128 + t * 2]     = h0;
        ((uint32_t*)g_ah)[i * 128 + t * 2 + 1] = h1;
        ((uint32_t*)g_al)[i * 128 + t * 2]     = l0;
        ((uint32_t*)g_al)[i * 128 + t * 2 + 1] = l1;
    }
}

// ---------------- LayerNorm: 4 rows/block, float4/thread ----------------------
__global__ void k_ln(const float* __restrict__ gamma,
                     const float* __restrict__ beta,
                     float* __restrict__ out) {
    int t = threadIdx.x;
    int r = t >> 6, cq = t & 63;
    int row = blockIdx.x * 4 + r;
    int warp = t >> 5, lane = t & 31;
    __shared__ float red[8], red2[8];

    float4 v = *(const float4*)&g_fin[row * 256 + cq * 4];
    float s = v.x + v.y + v.z + v.w;
#pragma unroll
    for (int o = 16; o; o >>= 1) s += __shfl_xor_sync(0xffffffffu, s, o);
    if (lane == 0) red[warp] = s;
    __syncthreads();
    float mu = (red[r * 2] + red[r * 2 + 1]) * (1.0f / 256.0f);

    float dx = v.x - mu, dy = v.y - mu, dz = v.z - mu, dw = v.w - mu;
    float s2 = dx * dx + dy * dy + dz * dz + dw * dw;
#pragma unroll
    for (int o = 16; o; o >>= 1) s2 += __shfl_xor_sync(0xffffffffu, s2, o);
    if (lane == 0) red2[warp] = s2;
    __syncthreads();
    float var = (red2[r * 2] + red2[r * 2 + 1]) * (1.0f / 256.0f);
    float rs = rsqrtf(var + 1e-5f);

    float4 gm = *(const float4*)&gamma[cq * 4];
    float4 bt = *(const float4*)&beta[cq * 4];
    float4 o4;
    o4.x = dx * rs * gm.x + bt.x;
    o4.y = dy * rs * gm.y + bt.y;
    o4.z = dz * rs * gm.z + bt.z;
    o4.w = dw * rs * gm.w + bt.w;
    *(float4*)&out[row * 256 + cq * 4] = o4;
}

// ---------------- launch --------------------------------------------------------
extern "C" void kernel_launch(void* const* d_in, const int* in_sizes, int n_in,
                              void* d_out, int out_size) {
    const float* nf    = (const float*)d_in[0];
    const int*   ei    = (const int*)d_in[1];
    const float* in_w  = (const float*)d_in[2];
    const float* in_b  = (const float*)d_in[3];
    const float* out_w = (const float*)d_in[4];
    const float* out_b = (const float*)d_in[5];
    const float* p_w   = (const float*)d_in[6];
    const float* p_b   = (const float*)d_in[7];
    const float* gamma = (const float*)d_in[8];
    const float* beta  = (const float*)d_in[9];
    int E = in_sizes[1] / 2;

    // side stream + fork/join events (created once, on the uncaptured first call)
    static cudaStream_t s2 = [] { cudaStream_t s; cudaStreamCreateWithFlags(&s, cudaStreamNonBlocking); return s; }();
    static cudaEvent_t evF = [] { cudaEvent_t e; cudaEventCreateWithFlags(&e, cudaEventDisableTiming); return e; }();
    static cudaEvent_t evJ = [] { cudaEvent_t e; cudaEventCreateWithFlags(&e, cudaEventDisableTiming); return e; }();

    const int SMEM_64 = 2 * (2 * 64 + 2 * 128) * PITCH * 2;   // 110592 B (2 stages)
    cudaFuncSetAttribute(
        (const void*)k_mgemm<64, 0, 0, 0, true,  false, false, true>,
        cudaFuncAttributeMaxDynamicSharedMemorySize, SMEM_64);
    cudaFuncSetAttribute(
        (const void*)k_mgemm<64, 1, 1, 1, false, true,  true,  false>,
        cudaFuncAttributeMaxDynamicSharedMemorySize, SMEM_64);

    // fork: Wc fusion pipeline runs concurrently with gemm1+attn
    cudaEventRecord(evF, 0);
    cudaStreamWaitEvent(s2, evF, 0);
    k_wc<<<dim3(8, 8, 4), 256, 0, s2>>>(p_w, out_w, out_b, p_b);
    k_wcr<<<256, 128, 0, s2>>>();
    cudaEventRecord(evJ, s2);

    k_init_bitmap<<<(NN * WPR) / 256, 256>>>();
    k_edges<<<(E + 255) / 256, 256>>>(ei, E);
    k_split_in<<<(NA + NW + 255) / 256, 256>>>(nf, in_w);
    k_mgemm<64, 0, 0, 0, true, false, false, true>
        <<<dim3(TD / 128, NN / 64), 256, SMEM_64>>>(in_b, nullptr, TD);
    k_attn<<<NN, 256>>>();

    // join: gemm2 needs g_ch/g_cl/g_bc
    cudaStreamWaitEvent(0, evJ, 0);
    k_mgemm<64, 1, 1, 1, false, true, true, false>
        <<<dim3(DD / 128, NN / 64), 256, SMEM_64>>>(nullptr, nf, DD);
    k_ln<<<NN / 4, 256>>>(gamma, beta, (float*)d_out);
}